// round 1
// baseline (speedup 1.0000x reference)
#include <cuda_runtime.h>
#include <cuda_bf16.h>

#define FEAT      4096
#define NTHREADS  256
#define PER       16          // FEAT / NTHREADS
#define SEL_RANK  2048u       // 0-indexed rank of smallest KEPT element
#define SCALE     2.0f        // FEAT / NACTIVE

// monotone fp32 -> u32 key (ascending float order == ascending uint order)
__device__ __forceinline__ unsigned int fkey(float f) {
    unsigned int u = __float_as_uint(f);
    return u ^ ((unsigned int)((int)u >> 31) | 0x80000000u);
}
// inverse key -> fp32
__device__ __forceinline__ float kinv(unsigned int k) {
    unsigned int u = (k & 0x80000000u) ? (k ^ 0x80000000u) : ~k;
    return __uint_as_float(u);
}

__global__ __launch_bounds__(NTHREADS)
void MaxoutDynamic_kernel(const float* __restrict__ feat, float* __restrict__ out) {
    __shared__ unsigned int hist[2048];
    __shared__ unsigned int wsum[8];
    __shared__ unsigned int s_prefix;
    __shared__ unsigned int s_rank;

    const int tid = threadIdx.x;
    const unsigned int lane = tid & 31;
    const unsigned int wid  = tid >> 5;
    const size_t row_off = (size_t)blockIdx.x * FEAT;

    // ---- load row into registers (keys only) ----
    const float4* in4 = reinterpret_cast<const float4*>(feat + row_off);
    unsigned int key[PER];
    #pragma unroll
    for (int j = 0; j < 4; j++) {
        float4 v = in4[tid + NTHREADS * j];
        key[4 * j + 0] = fkey(v.x);
        key[4 * j + 1] = fkey(v.y);
        key[4 * j + 2] = fkey(v.z);
        key[4 * j + 3] = fkey(v.w);
    }

    // ---- MSB-first radix select: digits of 11 / 11 / 10 bits ----
    unsigned int prefix = 0;
    unsigned int himask = 0;
    unsigned int rank = SEL_RANK;

    #pragma unroll
    for (int p = 0; p < 3; p++) {
        const int shift            = (p == 0) ? 21 : (p == 1) ? 10 : 0;
        const unsigned int nbins   = (p == 2) ? 1024u : 2048u;
        const unsigned int dmask   = nbins - 1u;
        const int chunk            = (int)(nbins / NTHREADS);   // 8, 8, 4

        // zero histogram
        for (int i = tid; i < (int)nbins; i += NTHREADS) hist[i] = 0u;
        __syncthreads();

        // histogram candidates
        #pragma unroll
        for (int e = 0; e < PER; e++) {
            unsigned int k = key[e];
            if ((k & himask) == prefix)
                atomicAdd(&hist[(k >> shift) & dmask], 1u);
        }
        __syncthreads();

        // per-thread chunk sum
        unsigned int csum = 0;
        const int base = tid * chunk;
        #pragma unroll 8
        for (int i = 0; i < chunk; i++) csum += hist[base + i];

        // block exclusive scan of chunk sums (warp scan + warp-sum scan)
        unsigned int v = csum;
        #pragma unroll
        for (int off = 1; off < 32; off <<= 1) {
            unsigned int t = __shfl_up_sync(0xFFFFFFFFu, v, off);
            if (lane >= (unsigned)off) v += t;
        }
        if (lane == 31) wsum[wid] = v;
        __syncthreads();
        if (tid < 32) {
            unsigned int w = (tid < 8) ? wsum[tid] : 0u;
            #pragma unroll
            for (int off = 1; off < 8; off <<= 1) {
                unsigned int t = __shfl_up_sync(0xFFFFFFFFu, w, off);
                if (lane >= (unsigned)off) w += t;
            }
            if (tid < 8) wsum[tid] = w;   // inclusive warp sums
        }
        __syncthreads();

        const unsigned int base_excl = (v - csum) + (wid ? wsum[wid - 1] : 0u);

        // the thread whose chunk contains the target walks its bins
        if (rank >= base_excl && rank < base_excl + csum) {
            unsigned int r = rank - base_excl;
            unsigned int d = 0;
            #pragma unroll 8
            for (int i = 0; i < chunk; i++) {
                unsigned int c = hist[base + i];
                if (r < c) { d = (unsigned int)(base + i); break; }
                r -= c;
            }
            s_prefix = prefix | (d << shift);
            s_rank   = r;
        }
        __syncthreads();

        prefix = s_prefix;
        rank   = s_rank;
        himask |= (dmask << shift);
        __syncthreads();   // s_prefix/s_rank consumed + hist reads done before re-zero
    }

    const unsigned int K = prefix;   // full 32-bit threshold key (rank-2048 element)

    // ---- predicated scaled writeback ----
    float4* out4 = reinterpret_cast<float4*>(out + row_off);
    #pragma unroll
    for (int j = 0; j < 4; j++) {
        float4 r;
        unsigned int k0 = key[4 * j + 0];
        unsigned int k1 = key[4 * j + 1];
        unsigned int k2 = key[4 * j + 2];
        unsigned int k3 = key[4 * j + 3];
        r.x = (k0 >= K) ? SCALE * kinv(k0) : 0.0f;
        r.y = (k1 >= K) ? SCALE * kinv(k1) : 0.0f;
        r.z = (k2 >= K) ? SCALE * kinv(k2) : 0.0f;
        r.w = (k3 >= K) ? SCALE * kinv(k3) : 0.0f;
        out4[tid + NTHREADS * j] = r;
    }
}

extern "C" void kernel_launch(void* const* d_in, const int* in_sizes, int n_in,
                              void* d_out, int out_size) {
    const float* feat = (const float*)d_in[0];
    float* out = (float*)d_out;
    const int rows = in_sizes[0] / FEAT;   // 16384
    MaxoutDynamic_kernel<<<rows, NTHREADS>>>(feat, out);
}

// round 2
// speedup vs baseline: 1.0722x; 1.0722x over previous
#include <cuda_runtime.h>
#include <cuda_bf16.h>

#define FEAT      4096
#define NTHREADS  256
#define PER       16          // FEAT / NTHREADS
#define SEL_RANK  2048u       // 0-indexed rank of smallest KEPT element
#define SCALE     2.0f        // FEAT / NACTIVE

// monotone fp32 -> u32 key (ascending float order == ascending uint order)
__device__ __forceinline__ unsigned int fkey(float f) {
    unsigned int u = __float_as_uint(f);
    return u ^ ((unsigned int)((int)u >> 31) | 0x80000000u);
}
// inverse key -> fp32 bits (branchless)
__device__ __forceinline__ float kinv(unsigned int k) {
    unsigned int m = (unsigned int)((int)(~k) >> 31) | 0x80000000u;
    return __uint_as_float(k ^ m);
}

__global__ __launch_bounds__(NTHREADS)
void MaxoutDynamic_kernel(const float* __restrict__ feat, float* __restrict__ out) {
    __shared__ __align__(16) unsigned int hist[2048];
    __shared__ unsigned int wsum[8];
    __shared__ unsigned int s_pr[2];   // {prefix, rank}

    const int tid = threadIdx.x;
    const unsigned int lane = tid & 31;
    const unsigned int wid  = tid >> 5;
    const size_t row_off = (size_t)blockIdx.x * FEAT;

    // ---- load row (keys only), zero histogram while loads are in flight ----
    const float4* in4 = reinterpret_cast<const float4*>(feat + row_off);
    float4 v0 = in4[tid];
    float4 v1 = in4[tid + 256];
    float4 v2 = in4[tid + 512];
    float4 v3 = in4[tid + 768];

    const uint4 z4 = make_uint4(0u, 0u, 0u, 0u);
    reinterpret_cast<uint4*>(hist)[tid]       = z4;
    reinterpret_cast<uint4*>(hist)[tid + 256] = z4;

    unsigned int key[PER];
    key[0]  = fkey(v0.x); key[1]  = fkey(v0.y); key[2]  = fkey(v0.z); key[3]  = fkey(v0.w);
    key[4]  = fkey(v1.x); key[5]  = fkey(v1.y); key[6]  = fkey(v1.z); key[7]  = fkey(v1.w);
    key[8]  = fkey(v2.x); key[9]  = fkey(v2.y); key[10] = fkey(v2.z); key[11] = fkey(v2.w);
    key[12] = fkey(v3.x); key[13] = fkey(v3.y); key[14] = fkey(v3.z); key[15] = fkey(v3.w);

    // ---- sign pre-pass: count positive-side keys (top bit set), no atomics ----
    unsigned int cpos = 0;
    #pragma unroll
    for (int e = 0; e < PER; e++) cpos += key[e] >> 31;
    #pragma unroll
    for (int off = 16; off; off >>= 1) cpos += __shfl_xor_sync(0xFFFFFFFFu, cpos, off);
    if (lane == 0) wsum[wid] = cpos;
    __syncthreads();   // also orders hist zeroing before pass-1 atomics

    unsigned int total_pos = 0;
    #pragma unroll
    for (int w = 0; w < 8; w++) total_pos += wsum[w];
    const unsigned int cneg = FEAT - total_pos;

    unsigned int prefix, rank;
    if (SEL_RANK < cneg) { prefix = 0u;          rank = SEL_RANK;        }
    else                 { prefix = 0x80000000u; rank = SEL_RANK - cneg; }
    unsigned int himask = 0x80000000u;

    // ---- radix select on remaining 31 bits: digits 11 / 10 / 10 ----
    #pragma unroll
    for (int p = 0; p < 3; p++) {
        const int shift          = (p == 0) ? 20 : (p == 1) ? 10 : 0;
        const unsigned int nbins = (p == 0) ? 2048u : 1024u;
        const unsigned int dmask = nbins - 1u;
        const int chunk          = (p == 0) ? 8 : 4;   // bins per thread

        // histogram candidates (pass 0: ~half the row; passes 1-2: ~tens)
        #pragma unroll
        for (int e = 0; e < PER; e++) {
            unsigned int k = key[e];
            if ((k & himask) == prefix)
                atomicAdd(&hist[(k >> shift) & dmask], 1u);
        }
        __syncthreads();

        // read chunk into regs, re-zero in place (fused), sum
        unsigned int c[8];
        unsigned int csum;
        if (chunk == 8) {
            uint4 a = reinterpret_cast<uint4*>(hist)[2 * tid];
            uint4 b = reinterpret_cast<uint4*>(hist)[2 * tid + 1];
            reinterpret_cast<uint4*>(hist)[2 * tid]     = z4;
            reinterpret_cast<uint4*>(hist)[2 * tid + 1] = z4;
            c[0] = a.x; c[1] = a.y; c[2] = a.z; c[3] = a.w;
            c[4] = b.x; c[5] = b.y; c[6] = b.z; c[7] = b.w;
            csum = c[0] + c[1] + c[2] + c[3] + c[4] + c[5] + c[6] + c[7];
        } else {
            uint4 a = reinterpret_cast<uint4*>(hist)[tid];
            reinterpret_cast<uint4*>(hist)[tid] = z4;
            c[0] = a.x; c[1] = a.y; c[2] = a.z; c[3] = a.w;
            c[4] = 0; c[5] = 0; c[6] = 0; c[7] = 0;
            csum = c[0] + c[1] + c[2] + c[3];
        }

        // warp inclusive scan of chunk sums
        unsigned int v = csum;
        #pragma unroll
        for (int off = 1; off < 32; off <<= 1) {
            unsigned int t = __shfl_up_sync(0xFFFFFFFFu, v, off);
            if (lane >= (unsigned)off) v += t;
        }
        if (lane == 31) wsum[wid] = v;
        __syncthreads();

        // cross-warp exclusive base: sum of prior warp totals (<=7 LDS)
        unsigned int wb = 0;
        #pragma unroll
        for (int w = 0; w < 7; w++) if (w < (int)wid) wb += wsum[w];
        const unsigned int base_excl = wb + (v - csum);

        // the thread whose chunk contains the target walks its registers
        if (rank - base_excl < csum) {   // unsigned trick: in [base_excl, base_excl+csum)
            unsigned int r = rank - base_excl;
            unsigned int d = 0;
            #pragma unroll
            for (int i = 0; i < chunk; i++) {
                if (r < c[i]) { d = (unsigned int)(tid * chunk + i); break; }
                r -= c[i];
            }
            s_pr[0] = prefix | (d << shift);
            s_pr[1] = r;
        }
        __syncthreads();   // publishes s_pr; hist fully re-zeroed before next atomics

        prefix = s_pr[0];
        rank   = s_pr[1];
        himask |= dmask << shift;
    }

    const unsigned int K = prefix;   // full 32-bit key of the rank-2048 element

    // ---- predicated scaled writeback ----
    float4* out4 = reinterpret_cast<float4*>(out + row_off);
    #pragma unroll
    for (int j = 0; j < 4; j++) {
        float4 r;
        unsigned int k0 = key[4 * j + 0];
        unsigned int k1 = key[4 * j + 1];
        unsigned int k2 = key[4 * j + 2];
        unsigned int k3 = key[4 * j + 3];
        r.x = (k0 >= K) ? SCALE * kinv(k0) : 0.0f;
        r.y = (k1 >= K) ? SCALE * kinv(k1) : 0.0f;
        r.z = (k2 >= K) ? SCALE * kinv(k2) : 0.0f;
        r.w = (k3 >= K) ? SCALE * kinv(k3) : 0.0f;
        out4[tid + NTHREADS * j] = r;
    }
}

extern "C" void kernel_launch(void* const* d_in, const int* in_sizes, int n_in,
                              void* d_out, int out_size) {
    const float* feat = (const float*)d_in[0];
    float* out = (float*)d_out;
    const int rows = in_sizes[0] / FEAT;   // 16384
    MaxoutDynamic_kernel<<<rows, NTHREADS>>>(feat, out);
}